// round 17
// baseline (speedup 1.0000x reference)
#include <cuda_runtime.h>
#include <cuda_fp16.h>
#include <math.h>
#include <stdint.h>

#define DIM   2048
#define NH    16
#define NKV   4
#define HD    128
#define BB    2
#define SL    2048
#define MROWS (BB*SL)                 // 4096
#define QKV_N ((NH + 2*NKV)*HD)       // 3072

// ---------------- scratch (static device globals; no allocations) -----------
__device__ __half g_q   [BB*NH *SL*HD];        // fp16 (qscale folded in)
__device__ __half g_k   [BB*NKV*SL*HD];        // fp16
__device__ __half g_v   [BB*NKV*SL*HD];        // fp16 [b][kv][s][d]
__device__ __half g_attn[MROWS * DIM];         // fp16 (O-proj A operand)
__device__ __half g_xh  [MROWS * DIM];         // fp16 copy of x
__device__ __half g_wqh [QKV_N * DIM];         // fp16 copy of wqkv
__device__ __half g_woh [DIM   * DIM];         // fp16 copy of wo

__device__ __forceinline__ uint32_t pack_h2(float lo, float hi) {
    __half2 h = __floats2half2_rn(lo, hi);
    return *(uint32_t*)&h;
}

__device__ __forceinline__ void mma_f16(float c[4],
                                        uint32_t a0, uint32_t a1,
                                        uint32_t a2, uint32_t a3,
                                        uint32_t b0, uint32_t b1) {
    asm volatile(
        "mma.sync.aligned.m16n8k16.row.col.f32.f16.f16.f32 "
        "{%0,%1,%2,%3},{%4,%5,%6,%7},{%8,%9},{%0,%1,%2,%3};"
        : "+f"(c[0]), "+f"(c[1]), "+f"(c[2]), "+f"(c[3])
        : "r"(a0), "r"(a1), "r"(a2), "r"(a3), "r"(b0), "r"(b1));
}

__device__ __forceinline__ void ldsm4(uint32_t& r0, uint32_t& r1,
                                      uint32_t& r2, uint32_t& r3,
                                      uint32_t addr) {
    asm volatile("ldmatrix.sync.aligned.m8n8.x4.shared.b16 {%0,%1,%2,%3}, [%4];"
                 : "=r"(r0), "=r"(r1), "=r"(r2), "=r"(r3) : "r"(addr));
}

__device__ __forceinline__ void ldsm4t(uint32_t& r0, uint32_t& r1,
                                       uint32_t& r2, uint32_t& r3,
                                       uint32_t addr) {
    asm volatile("ldmatrix.sync.aligned.m8n8.x4.trans.shared.b16 {%0,%1,%2,%3}, [%4];"
                 : "=r"(r0), "=r"(r1), "=r"(r2), "=r"(r3) : "r"(addr));
}

__device__ __forceinline__ void cp16(void* smem, const void* g) {
    uint32_t s = (uint32_t)__cvta_generic_to_shared(smem);
    asm volatile("cp.async.cg.shared.global [%0], [%1], 16;"
                 :: "r"(s), "l"(g) : "memory");
}
#define CP_COMMIT() asm volatile("cp.async.commit_group;" ::: "memory")
#define CP_WAIT1()  asm volatile("cp.async.wait_group 1;"  ::: "memory")
#define CP_WAIT0()  asm volatile("cp.async.wait_group 0;"  ::: "memory")

// ---------------------------------------------------------------------------
// fp32 -> fp16 convert for all three GEMM operands (one launch).
// ---------------------------------------------------------------------------
__global__ void conv3_f16(const float* __restrict__ x,
                          const float* __restrict__ wq,
                          const float* __restrict__ wo) {
    const int gs = gridDim.x * blockDim.x;
    const int t  = blockIdx.x * blockDim.x + threadIdx.x;
    const int n1 = MROWS * DIM / 4, n2 = QKV_N * DIM / 4, n3 = DIM * DIM / 4;

    for (int i = t; i < n1; i += gs) {
        float4 v = ((const float4*)x)[i];
        ((uint2*)g_xh)[i] = make_uint2(pack_h2(v.x, v.y), pack_h2(v.z, v.w));
    }
    for (int i = t; i < n2; i += gs) {
        float4 v = ((const float4*)wq)[i];
        ((uint2*)g_wqh)[i] = make_uint2(pack_h2(v.x, v.y), pack_h2(v.z, v.w));
    }
    for (int i = t; i < n3; i += gs) {
        float4 v = ((const float4*)wo)[i];
        ((uint2*)g_woh)[i] = make_uint2(pack_h2(v.x, v.y), pack_h2(v.z, v.w));
    }
}

// ---------------------------------------------------------------------------
// Shared GEMM mainloop macro: CTA tile 128x256, warp tile 64x64, fp16 mma,
// 3-stage cp.async, K-chunk 64 halves, pitch 72.
// ---------------------------------------------------------------------------
#define GP      72
#define ASTG    (128 * GP)
#define BSTG    (256 * GP)
#define STG_TOT (ASTG + BSTG)                  // halves
#define GEMM_SMEM (3 * STG_TOT * 2)            // 165888 B

#define G_FILL(buf, k0)                                                       \
    {                                                                         \
        __half* As_ = smh + (size_t)(buf) * STG_TOT;                          \
        __half* Bs_ = As_ + ASTG;                                             \
        _Pragma("unroll")                                                     \
        for (int it = 0; it < 12; it++) {                                     \
            int idx = tid + it * 256;                                         \
            if (idx < 1024) {                                                 \
                int r = idx >> 3, cc = (idx & 7) << 3;                        \
                cp16(As_ + r * GP + cc, Ab + (size_t)r * K + (k0) + cc);      \
            } else {                                                          \
                int i2 = idx - 1024;                                          \
                int r = i2 >> 3, cc = (i2 & 7) << 3;                          \
                cp16(Bs_ + r * GP + cc, Bb + (size_t)r * K + (k0) + cc);      \
            }                                                                 \
        }                                                                     \
    }

#define GEMM_MAINLOOP()                                                       \
    G_FILL(0, 0);  CP_COMMIT();                                               \
    G_FILL(1, 64); CP_COMMIT();                                               \
    for (int ch = 0; ch < nch; ch++) {                                        \
        const int buf = ch % 3;                                               \
        if (ch + 1 < nch) CP_WAIT1(); else CP_WAIT0();                        \
        __syncthreads();                                                      \
        const uint32_t sA = sbase + (uint32_t)(buf * STG_TOT) * 2u;           \
        const uint32_t sB = sA + (uint32_t)ASTG * 2u;                         \
        _Pragma("unroll")                                                     \
        for (int kk = 0; kk < 64; kk += 16) {                                 \
            uint32_t a[4][4], b[8][2];                                        \
            _Pragma("unroll")                                                 \
            for (int f = 0; f < 4; f++)                                       \
                ldsm4(a[f][0], a[f][1], a[f][2], a[f][3],                     \
                      sA + offA + (uint32_t)((f * 16 * GP + kk) * 2));        \
            _Pragma("unroll")                                                 \
            for (int gp = 0; gp < 4; gp++)                                    \
                ldsm4(b[2 * gp][0], b[2 * gp][1],                             \
                      b[2 * gp + 1][0], b[2 * gp + 1][1],                     \
                      sB + offB + (uint32_t)((gp * 16 * GP + kk) * 2));       \
            _Pragma("unroll")                                                 \
            for (int f = 0; f < 4; f++)                                       \
                _Pragma("unroll")                                             \
                for (int g = 0; g < 8; g++)                                   \
                    mma_f16(c[f][g], a[f][0], a[f][1], a[f][2], a[f][3],      \
                            b[g][0], b[g][1]);                                \
        }                                                                     \
        if (ch + 2 < nch) { G_FILL((ch + 2) % 3, (ch + 2) * 64); CP_COMMIT(); } \
    }

// ---------------------------------------------------------------------------
// Generic C(fp32) = A * B^T  (used for the output projection).
// ---------------------------------------------------------------------------
__global__ __launch_bounds__(256, 1)
void hgemm(const __half* __restrict__ A, const __half* __restrict__ B,
           float* __restrict__ C, int M, int N, int K) {
    extern __shared__ __half smh[];
    const uint32_t sbase = (uint32_t)__cvta_generic_to_shared(smh);

    const int tid  = threadIdx.x;
    const int lane = tid & 31;
    const int warp = tid >> 5;
    const int wm   = warp & 1;
    const int wn   = warp >> 1;
    const int gid  = lane >> 2;
    const int tig  = lane & 3;
    const int l8   = lane & 7;
    const int g8   = lane >> 3;

    const int m0 = blockIdx.y * 128;
    const int n0 = blockIdx.x * 256;
    const __half* Ab = A + (size_t)m0 * K;
    const __half* Bb = B + (size_t)n0 * K;

    const uint32_t offA = (uint32_t)(((wm * 64 + l8 + (g8 & 1) * 8) * GP
                                      + (g8 >> 1) * 8) * 2);
    const uint32_t offB = (uint32_t)(((wn * 64 + l8 + (g8 >> 1) * 8) * GP
                                      + (g8 & 1) * 8) * 2);

    float c[4][8][4] = {};
    const int nch = K / 64;

    GEMM_MAINLOOP();

#pragma unroll
    for (int f = 0; f < 4; f++) {
        int row = m0 + wm * 64 + f * 16 + gid;
#pragma unroll
        for (int g = 0; g < 8; g++) {
            int col = n0 + wn * 64 + g * 8 + 2 * tig;
            *(float2*)&C[(size_t)row * N + col] =
                make_float2(c[f][g][0], c[f][g][1]);
            *(float2*)&C[(size_t)(row + 8) * N + col] =
                make_float2(c[f][g][2], c[f][g][3]);
        }
    }
}

// ---------------------------------------------------------------------------
// QKV GEMM with FUSED RMSNorm + RoPE epilogue.
// Tile n-cols 256 = exactly 2 heads; bx 0-7 -> Q heads, 8-9 -> K, 10-11 -> V.
// ssq per (row, head): quad shuffles + 2-warp smem combine (reuses stage smem).
// Q/K: normalize * w, RoPE, (Q: * log2e/sqrt(HD)), store fp16 to g_q/g_k.
// V: pack fp16 to g_v.
// ---------------------------------------------------------------------------
__global__ __launch_bounds__(256, 1)
void hgemm_qkv(const __half* __restrict__ A, const __half* __restrict__ B,
               const float* __restrict__ qnw, const float* __restrict__ knw,
               const float* __restrict__ fcos, const float* __restrict__ fsin) {
    extern __shared__ __half smh[];
    const uint32_t sbase = (uint32_t)__cvta_generic_to_shared(smh);

    const int tid  = threadIdx.x;
    const int lane = tid & 31;
    const int warp = tid >> 5;
    const int wm   = warp & 1;
    const int wn   = warp >> 1;
    const int gid  = lane >> 2;
    const int tig  = lane & 3;
    const int l8   = lane & 7;
    const int g8   = lane >> 3;

    const int m0 = blockIdx.y * 128;
    const int n0 = blockIdx.x * 256;
    const int K  = DIM;
    const __half* Ab = A + (size_t)m0 * K;
    const __half* Bb = B + (size_t)n0 * K;

    const uint32_t offA = (uint32_t)(((wm * 64 + l8 + (g8 & 1) * 8) * GP
                                      + (g8 >> 1) * 8) * 2);
    const uint32_t offB = (uint32_t)(((wn * 64 + l8 + (g8 >> 1) * 8) * GP
                                      + (g8 & 1) * 8) * 2);

    float c[4][8][4] = {};
    const int nch = K / 64;

    GEMM_MAINLOOP();

    // ---------------- fused epilogue ----------------
    const int hg   = 2 * blockIdx.x + (wn >> 1);     // global head 0..23
    const int bidx = m0 / SL;                        // batch (128 | 2048)
    const int s0   = m0 % SL;                        // token base
    const int dbase = (wn & 1) * 64;                 // d offset of this warp

    if (hg < 20) {
        // ---- Q/K: RMSNorm + RoPE ----
        __syncthreads();                             // mainloop smem dead
        float* red = (float*)smh;                    // [4 warps-wn][128 rows]

#pragma unroll
        for (int f = 0; f < 4; f++) {
            float sA = 0.0f, sB = 0.0f;
#pragma unroll
            for (int g = 0; g < 8; g++) {
                sA += c[f][g][0] * c[f][g][0] + c[f][g][1] * c[f][g][1];
                sB += c[f][g][2] * c[f][g][2] + c[f][g][3] * c[f][g][3];
            }
            sA += __shfl_xor_sync(0xffffffffu, sA, 1);
            sA += __shfl_xor_sync(0xffffffffu, sA, 2);
            sB += __shfl_xor_sync(0xffffffffu, sB, 1);
            sB += __shfl_xor_sync(0xffffffffu, sB, 2);
            if (tig == 0) {
                red[wn * 128 + wm * 64 + f * 16 + gid]     = sA;
                red[wn * 128 + wm * 64 + f * 16 + gid + 8] = sB;
            }
        }
        __syncthreads();

        const float* w = (hg < NH) ? qnw : knw;
        const float scl = (hg < NH) ? (1.4426950408889634f * 0.08838834764831845f)
                                    : 1.0f;          // log2e/sqrt(128) for Q
        const int wp = wn & 2;                       // partner-pair base (0 or 2)
        __half* outbase = (hg < NH)
            ? g_q + ((size_t)(bidx * NH  + hg)      * SL) * HD
            : g_k + ((size_t)(bidx * NKV + hg - NH) * SL) * HD;

#pragma unroll
        for (int f = 0; f < 4; f++) {
            int rA = wm * 64 + f * 16 + gid;
            int rB = rA + 8;
            float ssqA = red[wp * 128 + rA] + red[(wp + 1) * 128 + rA];
            float ssqB = red[wp * 128 + rB] + red[(wp + 1) * 128 + rB];
            float rnA = rsqrtf(ssqA * (1.0f / HD) + 1.1920929e-07f);
            float rnB = rsqrtf(ssqB * (1.0f / HD) + 1.1920929e-07f);
            int sTA = s0 + rA, sTB = s0 + rB;
#pragma unroll
            for (int g = 0; g < 8; g++) {
                int d = dbase + g * 8 + 2 * tig;
                float2 wv  = *(const float2*)&w[d];
                float2 fcA = *(const float2*)&fcos[(size_t)sTA * HD + d];
                float2 fsA = *(const float2*)&fsin[(size_t)sTA * HD + d];
                float xe = c[f][g][0] * rnA * wv.x;
                float xo = c[f][g][1] * rnA * wv.y;
                *(uint32_t*)(outbase + (size_t)sTA * HD + d) =
                    pack_h2((xe * fcA.x - xo * fsA.x) * scl,
                            (xo * fcA.y + xe * fsA.y) * scl);

                float2 fcB = *(const float2*)&fcos[(size_t)sTB * HD + d];
                float2 fsB = *(const float2*)&fsin[(size_t)sTB * HD + d];
                xe = c[f][g][2] * rnB * wv.x;
                xo = c[f][g][3] * rnB * wv.y;
                *(uint32_t*)(outbase + (size_t)sTB * HD + d) =
                    pack_h2((xe * fcB.x - xo * fsB.x) * scl,
                            (xo * fcB.y + xe * fsB.y) * scl);
            }
        }
    } else {
        // ---- V: plain fp16 store ----
        __half* outbase = g_v + ((size_t)(bidx * NKV + hg - 20) * SL) * HD;
#pragma unroll
        for (int f = 0; f < 4; f++) {
            int sTA = s0 + wm * 64 + f * 16 + gid;
            int sTB = sTA + 8;
#pragma unroll
            for (int g = 0; g < 8; g++) {
                int d = dbase + g * 8 + 2 * tig;
                *(uint32_t*)(outbase + (size_t)sTA * HD + d) =
                    pack_h2(c[f][g][0], c[f][g][1]);
                *(uint32_t*)(outbase + (size_t)sTB * HD + d) =
                    pack_h2(c[f][g][2], c[f][g][3]);
            }
        }
    }
}

// ---------------------------------------------------------------------------
// Flash attention, fp16 m16n8k16, NO-MAX softmax with -1 exponent shift.
// QT=128 (8 warps x 16 rows), KT=64, cp.async double-buffered K/V.
// P C-frag == fp16 A-frag layout -> no shuffles in PV; V via ldmatrix.trans.
// ---------------------------------------------------------------------------
#define FQT  128
#define FKT  64
#define FP   136                               // halves pitch
#define KBUF(b) ((b) * FKT * FP)
#define VBUF(b) (2 * FKT * FP + (b) * FKT * FP)
#define FLASH_SMEM (4 * FKT * FP * 2)          // 69632 B

__global__ __launch_bounds__(256)
void flash_f16() {
    extern __shared__ __half smh[];
    const uint32_t sbase = (uint32_t)__cvta_generic_to_shared(smh);

    const int tid  = threadIdx.x;
    const int lane = tid & 31;
    const int warp = tid >> 5;
    const int gid  = lane >> 2;
    const int tig  = lane & 3;
    const int l8   = lane & 7;
    const int g8   = lane >> 3;
    const int wq   = warp * 16;

    const int qt = blockIdx.x, h = blockIdx.y, b = blockIdx.z;
    const int kvh = h >> 2;

    const __half* Qg = g_q + (((size_t)b * NH  + h  ) * SL + qt * FQT) * HD;
    const __half* Kg = g_k + (((size_t)b * NKV + kvh) * SL) * HD;
    const __half* Vg = g_v + (((size_t)b * NKV + kvh) * SL) * HD;

    // ---- stage Q into the (aliased) two K buffers via cp.async ----
#pragma unroll
    for (int it = 0; it < 8; it++) {
        int idx = tid + it * 256;               // 0..2047 16B chunks
        int r = idx >> 4, cc = (idx & 15) << 3;
        cp16(smh + r * FP + cc, Qg + (size_t)r * HD + cc);
    }
    CP_COMMIT(); CP_WAIT0();
    __syncthreads();

    const uint32_t offQ = (uint32_t)(((wq + l8 + (g8 & 1) * 8) * FP
                                      + (g8 >> 1) * 8) * 2);
    uint32_t qa[8][4];
#pragma unroll
    for (int ks = 0; ks < 8; ks++)
        ldsm4(qa[ks][0], qa[ks][1], qa[ks][2], qa[ks][3],
              sbase + offQ + (uint32_t)(ks * 16 * 2));
    __syncthreads();   // Q reads done before K fills overwrite the alias

    float c[16][4] = {};
    float l0 = 0.0f, l1 = 0.0f;

    const uint32_t offK = (uint32_t)(((l8 + (g8 >> 1) * 8) * FP
                                      + (g8 & 1) * 8) * 2);
    const uint32_t offV = (uint32_t)(((l8 + (g8 & 1) * 8) * FP
                                      + (g8 >> 1) * 8) * 2);

    const int NKT = SL / FKT;                  // 32

#define F_FILL(t)                                                             \
    {                                                                         \
        const __half* Kn = Kg + (size_t)(t) * FKT * HD;                       \
        const __half* Vn = Vg + (size_t)(t) * FKT * HD;                       \
        __half* kb = smh + KBUF((t) & 1);                                     \
        __half* vb = smh + VBUF((t) & 1);                                     \
        _Pragma("unroll")                                                     \
        for (int it = 0; it < 4; it++) {                                      \
            int idx = tid + it * 256;          /* 0..1023 */                  \
            int r = idx >> 4, cc = (idx & 15) << 3;                           \
            cp16(kb + r * FP + cc, Kn + (size_t)r * HD + cc);                 \
            cp16(vb + r * FP + cc, Vn + (size_t)r * HD + cc);                 \
        }                                                                     \
    }

    F_FILL(0);
    CP_COMMIT();

    for (int kt = 0; kt < NKT; kt++) {
        const int buf = kt & 1;
        if (kt + 1 < NKT) {
            F_FILL(kt + 1);
            CP_COMMIT();
            CP_WAIT1();
        } else {
            CP_WAIT0();
        }
        __syncthreads();

        const uint32_t sK = sbase + (uint32_t)(KBUF(buf) * 2);
        const uint32_t sV = sbase + (uint32_t)(VBUF(buf) * 2);

        // ---- S = Q * K^T : 8 k16-slabs x 8 key-groups ----
        float sc[8][4] = {};
#pragma unroll
        for (int ks = 0; ks < 8; ks++) {
#pragma unroll
            for (int jp = 0; jp < 4; jp++) {
                uint32_t b0, b1, b2, b3;
                ldsm4(b0, b1, b2, b3,
                      sK + offK + (uint32_t)((jp * 16 * FP + ks * 16) * 2));
                mma_f16(sc[2 * jp],     qa[ks][0], qa[ks][1], qa[ks][2], qa[ks][3], b0, b1);
                mma_f16(sc[2 * jp + 1], qa[ks][0], qa[ks][1], qa[ks][2], qa[ks][3], b2, b3);
            }
        }

        // ---- softmax (exp2, -1 shift) + pack P into fp16 A-frags ----
        uint32_t pa[4][4];
#pragma unroll
        for (int s = 0; s < 4; s++) {
            float pa0 = exp2f(sc[2*s][0] - 1.0f);
            float pa1 = exp2f(sc[2*s][1] - 1.0f);
            float pa2 = exp2f(sc[2*s][2] - 1.0f);
            float pa3 = exp2f(sc[2*s][3] - 1.0f);
            float pb0 = exp2f(sc[2*s+1][0] - 1.0f);
            float pb1 = exp2f(sc[2*s+1][1] - 1.0f);
            float pb2 = exp2f(sc[2*s+1][2] - 1.0f);
            float pb3 = exp2f(sc[2*s+1][3] - 1.0f);
            l0 += pa0 + pa1 + pb0 + pb1;
            l1 += pa2 + pa3 + pb2 + pb3;
            pa[s][0] = pack_h2(pa0, pa1);
            pa[s][1] = pack_h2(pa2, pa3);
            pa[s][2] = pack_h2(pb0, pb1);
            pa[s][3] = pack_h2(pb2, pb3);
        }

        // ---- O += P * V : 4 key-slabs x 8 d-group-pairs (ldmatrix.trans) ---
#pragma unroll
        for (int j = 0; j < 4; j++) {
#pragma unroll
            for (int dp = 0; dp < 8; dp++) {
                uint32_t b0, b1, b2, b3;
                ldsm4t(b0, b1, b2, b3,
                       sV + offV + (uint32_t)((j * 16 * FP + dp * 16) * 2));
                mma_f16(c[2 * dp],     pa[j][0], pa[j][1], pa[j][2], pa[j][3], b0, b1);
                mma_f16(c[2 * dp + 1], pa[j][0], pa[j][1], pa[j][2], pa[j][3], b2, b3);
            }
        }
        __syncthreads();
    }

    // ---- final l reduction across the quad, normalize + write fp16 ----
    l0 += __shfl_xor_sync(0xffffffffu, l0, 1);
    l0 += __shfl_xor_sync(0xffffffffu, l0, 2);
    l1 += __shfl_xor_sync(0xffffffffu, l1, 1);
    l1 += __shfl_xor_sync(0xffffffffu, l1, 2);
    float inv0 = 1.0f / l0, inv1 = 1.0f / l1;
    int row0 = qt * FQT + wq + gid;
#pragma unroll
    for (int j2 = 0; j2 < 16; j2++) {
        int col = h * HD + 8 * j2 + 2 * tig;
        *(uint32_t*)&g_attn[((size_t)b * SL + row0) * DIM + col] =
            pack_h2(c[j2][0] * inv0, c[j2][1] * inv0);
        *(uint32_t*)&g_attn[((size_t)b * SL + row0 + 8) * DIM + col] =
            pack_h2(c[j2][2] * inv1, c[j2][3] * inv1);
    }
}

// ---------------------------------------------------------------------------
extern "C" void kernel_launch(void* const* d_in, const int* in_sizes, int n_in,
                              void* d_out, int out_size) {
    const float* x    = (const float*)d_in[0];
    const float* wqkv = (const float*)d_in[1];
    const float* wo   = (const float*)d_in[2];
    const float* qnw  = (const float*)d_in[3];
    const float* knw  = (const float*)d_in[4];
    const float* fcos = (const float*)d_in[5];
    const float* fsin = (const float*)d_in[6];
    float* out = (float*)d_out;

    void *p_attn, *p_xh, *p_wqh, *p_woh;
    cudaGetSymbolAddress(&p_attn, g_attn);
    cudaGetSymbolAddress(&p_xh,   g_xh);
    cudaGetSymbolAddress(&p_wqh,  g_wqh);
    cudaGetSymbolAddress(&p_woh,  g_woh);

    cudaFuncSetAttribute(flash_f16,
                         cudaFuncAttributeMaxDynamicSharedMemorySize, FLASH_SMEM);
    cudaFuncSetAttribute(hgemm,
                         cudaFuncAttributeMaxDynamicSharedMemorySize, GEMM_SMEM);
    cudaFuncSetAttribute(hgemm_qkv,
                         cudaFuncAttributeMaxDynamicSharedMemorySize, GEMM_SMEM);

    // 0) convert all GEMM operands to fp16 (single launch)
    conv3_f16<<<1184, 256>>>(x, wqkv, wo);

    // 1) QKV projection with fused RMSNorm + RoPE epilogue
    hgemm_qkv<<<dim3(QKV_N / 256, MROWS / 128), 256, GEMM_SMEM>>>(
        (const __half*)p_xh, (const __half*)p_wqh, qnw, knw, fcos, fsin);

    // 2) Flash attention (fp16 mma)
    flash_f16<<<dim3(SL / FQT, NH, BB), 256, FLASH_SMEM>>>();

    // 3) Output projection (fp16 mma)
    hgemm<<<dim3(DIM / 256, MROWS / 128), 256, GEMM_SMEM>>>(
        (const __half*)p_attn, (const __half*)p_woh, out, MROWS, DIM, DIM);
}